// round 9
// baseline (speedup 1.0000x reference)
#include <cuda_runtime.h>
#include <cstdint>

#define B_ 16
#define N_ 256
#define S_ 4096
#define C_ 512
#define H_ 8
#define HD 64
#define NCHUNK 8
#define SCHUNK (S_ / NCHUNK)   // 512
#define PIPE 4                 // S split into 4 pipeline chunks of 1024 rows

// Scratch (allocation-free: __device__ globals)
__device__ float g_kproj[(size_t)B_ * S_ * C_];              // 134 MB
__device__ float g_qproj[(size_t)B_ * N_ * C_];              // 8 MB
__device__ float g_opart[(size_t)B_ * H_ * NCHUNK * N_ * HD]; // 32 MB
__device__ float g_divpart[(size_t)B_ * H_ * NCHUNK * N_];

__device__ __forceinline__ uint32_t tf32u(float x) {
    uint32_t u;
    asm("cvt.rna.tf32.f32 %0, %1;" : "=r"(u) : "f"(x));
    return u;
}

__device__ __forceinline__ void mma_tf32(
    float& c0, float& c1, float& c2, float& c3,
    uint32_t a0, uint32_t a1, uint32_t a2, uint32_t a3,
    uint32_t b0, uint32_t b1)
{
    asm volatile(
        "mma.sync.aligned.m16n8k8.row.col.f32.tf32.tf32.f32 "
        "{%0,%1,%2,%3}, {%4,%5,%6,%7}, {%8,%9}, {%0,%1,%2,%3};"
        : "+f"(c0), "+f"(c1), "+f"(c2), "+f"(c3)
        : "r"(a0), "r"(a1), "r"(a2), "r"(a3), "r"(b0), "r"(b1));
}

__device__ __forceinline__ void cp_async16(uint32_t dst, const void* src) {
    asm volatile("cp.async.cg.shared.global [%0], [%1], 16;" :: "r"(dst), "l"(src));
}

// ---------------------------------------------------------------------------
// tf32 tensor-core GEMM with 3-stage cp.async pipeline (R5 body).
// rowBase < 0 : contiguous rows m0 = blockIdx.x*128            (qproj)
// rowBase >= 0: chunked rows  m0 = b*S_ + rowBase + (bx&7)*128 (kproj chunk)
// ---------------------------------------------------------------------------
#define AS_STRIDE 36
#define WS_STRIDE 136
#define A_FLOATS (128 * AS_STRIDE)
#define STAGE_FLOATS (A_FLOATS + 32 * WS_STRIDE)
#define GEMM_SMEM_BYTES (3 * STAGE_FLOATS * 4)

__global__ __launch_bounds__(256) void gemm_tf32_kernel(
    const float* __restrict__ A, const float* __restrict__ W,
    float* __restrict__ Cout, int rowBase)
{
    extern __shared__ float smbuf[];
    uint32_t smbase;
    {
        uint64_t tmp = __cvta_generic_to_shared(smbuf);
        smbase = (uint32_t)tmp;
    }

    const int tid  = threadIdx.x;
    const int warp = tid >> 5, lane = tid & 31;
    const int wm = warp >> 2, wn = warp & 3;
    const int group = lane >> 2, tid4 = lane & 3;

    size_t m0;
    if (rowBase >= 0)
        m0 = (size_t)(blockIdx.x >> 3) * S_ + rowBase + (blockIdx.x & 7) * 128;
    else
        m0 = (size_t)blockIdx.x * 128;
    const int n0 = blockIdx.y * 128;

    int ar[4], ac4[4], wr[4], wc4[4];
#pragma unroll
    for (int i = 0; i < 4; i++) {
        int f = tid + i * 256;
        ar[i] = f >> 3;  ac4[i] = (f & 7) << 2;
        wr[i] = f >> 5;  wc4[i] = (f & 31) << 2;
    }

    float acc[4][4][4];
#pragma unroll
    for (int mf = 0; mf < 4; mf++)
#pragma unroll
        for (int nf = 0; nf < 4; nf++)
#pragma unroll
            for (int r = 0; r < 4; r++) acc[mf][nf][r] = 0.f;

#define ISSUE_STAGE(kt, s)                                                         \
    do {                                                                           \
        uint32_t sb = smbase + (uint32_t)((s) * STAGE_FLOATS) * 4;                 \
        _Pragma("unroll")                                                          \
        for (int i = 0; i < 4; i++) {                                              \
            cp_async16(sb + (uint32_t)(ar[i] * AS_STRIDE + ac4[i]) * 4,            \
                       A + (m0 + ar[i]) * C_ + (kt) * 32 + ac4[i]);                \
            cp_async16(sb + (uint32_t)(A_FLOATS + wr[i] * WS_STRIDE + wc4[i]) * 4, \
                       W + (size_t)((kt) * 32 + wr[i]) * C_ + n0 + wc4[i]);        \
        }                                                                          \
        asm volatile("cp.async.commit_group;");                                    \
    } while (0)

    ISSUE_STAGE(0, 0);
    ISSUE_STAGE(1, 1);

    for (int kt = 0; kt < 16; kt++) {
        const int s = kt % 3;
        if (kt < 14) asm volatile("cp.async.wait_group 1;");
        else         asm volatile("cp.async.wait_group 0;");
        __syncthreads();
        if (kt + 2 < 16) ISSUE_STAGE(kt + 2, (kt + 2) % 3);

        const float* As = smbuf + s * STAGE_FLOATS;
        const float* Ws = As + A_FLOATS;

#pragma unroll
        for (int ks = 0; ks < 4; ks++) {
            const int kb = ks * 8;
            uint32_t a[4][4], b[4][2];
#pragma unroll
            for (int mf = 0; mf < 4; mf++) {
                int r = wm * 64 + mf * 16 + group;
                a[mf][0] = tf32u(As[r * AS_STRIDE + kb + tid4]);
                a[mf][1] = tf32u(As[(r + 8) * AS_STRIDE + kb + tid4]);
                a[mf][2] = tf32u(As[r * AS_STRIDE + kb + tid4 + 4]);
                a[mf][3] = tf32u(As[(r + 8) * AS_STRIDE + kb + tid4 + 4]);
            }
#pragma unroll
            for (int nf = 0; nf < 4; nf++) {
                int c = wn * 32 + nf * 8 + group;
                b[nf][0] = tf32u(Ws[(kb + tid4) * WS_STRIDE + c]);
                b[nf][1] = tf32u(Ws[(kb + tid4 + 4) * WS_STRIDE + c]);
            }
#pragma unroll
            for (int mf = 0; mf < 4; mf++)
#pragma unroll
                for (int nf = 0; nf < 4; nf++)
                    mma_tf32(acc[mf][nf][0], acc[mf][nf][1],
                             acc[mf][nf][2], acc[mf][nf][3],
                             a[mf][0], a[mf][1], a[mf][2], a[mf][3],
                             b[nf][0], b[nf][1]);
        }
    }

#pragma unroll
    for (int mf = 0; mf < 4; mf++) {
#pragma unroll
        for (int nf = 0; nf < 4; nf++) {
            size_t r = m0 + wm * 64 + mf * 16 + group;
            int c = n0 + wn * 32 + nf * 8 + 2 * tid4;
            *(float2*)(Cout + r * C_ + c) =
                make_float2(acc[mf][nf][0], acc[mf][nf][1]);
            *(float2*)(Cout + (r + 8) * C_ + c) =
                make_float2(acc[mf][nf][2], acc[mf][nf][3]);
        }
    }
}

// ---------------------------------------------------------------------------
// Attention (R5 body): tensor-core QK^T and attn@V; chk offset for pipelining.
// ---------------------------------------------------------------------------
#define ST 68
#define ATTN_SMEM_FLOATS (256 * ST + 64 * ST + 64 * ST + 256 + 64)
#define ATTN_SMEM_BYTES (ATTN_SMEM_FLOATS * 4)

__global__ __launch_bounds__(256) void attn_kernel(const float* __restrict__ keyv,
                                                   int chkBase)
{
    extern __shared__ float sm[];
    float* sc     = sm;                 // [256][ST]
    float* Ks     = sm + 256 * ST;      // [64][ST]
    float* Vs     = Ks + 64 * ST;       // [64][ST]
    float* red    = Vs + 64 * ST;       // [4][64]
    float* colrcp = red + 256;          // [64]

    const int tid = threadIdx.x;
    const int warp = tid >> 5, lane = tid & 31;
    const int g = lane >> 2, t4 = lane & 3;
    const int chk = chkBase + blockIdx.x, h = blockIdx.y, b = blockIdx.z;
    const int rb = warp * 32;
    const int col = tid & 63, part = tid >> 6;

    uint32_t qa[2][8][4];
    {
        const float* qp = g_qproj + (size_t)b * N_ * C_ + h * HD;
#pragma unroll
        for (int mf = 0; mf < 2; mf++) {
            int r0 = rb + mf * 16 + g;
#pragma unroll
            for (int kb = 0; kb < 8; kb++) {
                qa[mf][kb][0] = tf32u(qp[(size_t)r0 * C_ + kb * 8 + t4] * 0.125f);
                qa[mf][kb][1] = tf32u(qp[(size_t)(r0 + 8) * C_ + kb * 8 + t4] * 0.125f);
                qa[mf][kb][2] = tf32u(qp[(size_t)r0 * C_ + kb * 8 + t4 + 4] * 0.125f);
                qa[mf][kb][3] = tf32u(qp[(size_t)(r0 + 8) * C_ + kb * 8 + t4 + 4] * 0.125f);
            }
        }
    }

    float oa[2][8][4];
#pragma unroll
    for (int mf = 0; mf < 2; mf++)
#pragma unroll
        for (int nf = 0; nf < 8; nf++)
#pragma unroll
            for (int r = 0; r < 4; r++) oa[mf][nf][r] = 0.f;
    float dv[2][2] = {{0.f, 0.f}, {0.f, 0.f}};

    for (int tile = 0; tile < SCHUNK / 64; tile++) {
        const int s0 = chk * SCHUNK + tile * 64;
#pragma unroll
        for (int i = 0; i < 4; i++) {
            int f = tid + i * 256;
            int row = f >> 4, c4 = (f & 15) << 2;
            size_t gb = (size_t)(b * S_ + s0 + row) * C_ + h * HD + c4;
            *(float4*)&Ks[row * ST + c4] = *(const float4*)(g_kproj + gb);
            *(float4*)&Vs[row * ST + c4] = *(const float4*)(keyv + gb);
        }
        __syncthreads();

        float sacc[2][8][4];
#pragma unroll
        for (int mf = 0; mf < 2; mf++)
#pragma unroll
            for (int nf = 0; nf < 8; nf++)
#pragma unroll
                for (int r = 0; r < 4; r++) sacc[mf][nf][r] = 0.f;
#pragma unroll
        for (int kb = 0; kb < 8; kb++) {
            uint32_t bfr[8][2];
#pragma unroll
            for (int nf = 0; nf < 8; nf++) {
                bfr[nf][0] = tf32u(Ks[(nf * 8 + g) * ST + kb * 8 + t4]);
                bfr[nf][1] = tf32u(Ks[(nf * 8 + g) * ST + kb * 8 + t4 + 4]);
            }
#pragma unroll
            for (int mf = 0; mf < 2; mf++)
#pragma unroll
                for (int nf = 0; nf < 8; nf++)
                    mma_tf32(sacc[mf][nf][0], sacc[mf][nf][1],
                             sacc[mf][nf][2], sacc[mf][nf][3],
                             qa[mf][kb][0], qa[mf][kb][1], qa[mf][kb][2], qa[mf][kb][3],
                             bfr[nf][0], bfr[nf][1]);
        }
#pragma unroll
        for (int mf = 0; mf < 2; mf++)
#pragma unroll
            for (int nf = 0; nf < 8; nf++) {
                int r = rb + mf * 16 + g;
                int c = nf * 8 + 2 * t4;
                *(float2*)&sc[r * ST + c] = make_float2(sacc[mf][nf][0], sacc[mf][nf][1]);
                *(float2*)&sc[(r + 8) * ST + c] = make_float2(sacc[mf][nf][2], sacc[mf][nf][3]);
            }
        __syncthreads();

        float psum = 0.f;
#pragma unroll 4
        for (int r = 0; r < 64; r++) {
            int i = (part * 64 + r) * ST + col;
            float e = __expf(sc[i]);
            sc[i] = e;
            psum += e;
        }
        red[part * 64 + col] = psum;
        __syncthreads();
        if (part == 0)
            colrcp[col] = 1.0f / (red[col] + red[64 + col] + red[128 + col] + red[192 + col]);
        __syncthreads();

#pragma unroll
        for (int kb = 0; kb < 8; kb++) {
            float cr0 = colrcp[kb * 8 + t4], cr1 = colrcp[kb * 8 + t4 + 4];
            uint32_t afr[2][4];
#pragma unroll
            for (int mf = 0; mf < 2; mf++) {
                int r = rb + mf * 16 + g;
                float f0 = sc[r * ST + kb * 8 + t4] * cr0;
                float f1 = sc[(r + 8) * ST + kb * 8 + t4] * cr0;
                float f2 = sc[r * ST + kb * 8 + t4 + 4] * cr1;
                float f3 = sc[(r + 8) * ST + kb * 8 + t4 + 4] * cr1;
                dv[mf][0] += f0 + f2;
                dv[mf][1] += f1 + f3;
                afr[mf][0] = tf32u(f0); afr[mf][1] = tf32u(f1);
                afr[mf][2] = tf32u(f2); afr[mf][3] = tf32u(f3);
            }
            uint32_t bfr[8][2];
#pragma unroll
            for (int nf = 0; nf < 8; nf++) {
                bfr[nf][0] = tf32u(Vs[(kb * 8 + t4) * ST + nf * 8 + g]);
                bfr[nf][1] = tf32u(Vs[(kb * 8 + t4 + 4) * ST + nf * 8 + g]);
            }
#pragma unroll
            for (int mf = 0; mf < 2; mf++)
#pragma unroll
                for (int nf = 0; nf < 8; nf++)
                    mma_tf32(oa[mf][nf][0], oa[mf][nf][1],
                             oa[mf][nf][2], oa[mf][nf][3],
                             afr[mf][0], afr[mf][1], afr[mf][2], afr[mf][3],
                             bfr[nf][0], bfr[nf][1]);
        }
        __syncthreads();
    }

#pragma unroll
    for (int mf = 0; mf < 2; mf++)
#pragma unroll
        for (int hh = 0; hh < 2; hh++) {
            float v = dv[mf][hh];
            v += __shfl_xor_sync(0xFFFFFFFF, v, 1);
            v += __shfl_xor_sync(0xFFFFFFFF, v, 2);
            if (t4 == 0) {
                int row = rb + mf * 16 + hh * 8 + g;
                g_divpart[(size_t)((b * H_ + h) * NCHUNK + chk) * N_ + row] = v;
            }
        }

    const size_t pbase = (size_t)((b * H_ + h) * NCHUNK + chk) * N_;
#pragma unroll
    for (int mf = 0; mf < 2; mf++)
#pragma unroll
        for (int nf = 0; nf < 8; nf++) {
            int r = rb + mf * 16 + g;
            int c = nf * 8 + 2 * t4;
            *(float2*)(g_opart + (pbase + r) * HD + c) =
                make_float2(oa[mf][nf][0], oa[mf][nf][1]);
            *(float2*)(g_opart + (pbase + r + 8) * HD + c) =
                make_float2(oa[mf][nf][2], oa[mf][nf][3]);
        }
}

// ---------------------------------------------------------------------------
__global__ __launch_bounds__(256) void finalize_kernel(float* __restrict__ out)
{
    int idx = blockIdx.x * 256 + threadIdx.x;
    int c512 = idx & 511;
    int n = (idx >> 9) & 255;
    int b = idx >> 17;
    int h = c512 >> 6, c = c512 & 63;
    float acc = 0.f, dvs = 0.f;
#pragma unroll
    for (int chk = 0; chk < NCHUNK; chk++) {
        size_t pidx = (size_t)((b * H_ + h) * NCHUNK + chk) * N_ + n;
        acc += g_opart[pidx * HD + c];
        dvs += g_divpart[pidx];
    }
    float r = acc / fmaxf(dvs, 1.0f);
    out[idx] = r;
    out[idx + (size_t)B_ * N_ * C_] = r;
}

// ---------------------------------------------------------------------------
extern "C" void kernel_launch(void* const* d_in, const int* in_sizes, int n_in,
                              void* d_out, int out_size)
{
    const float* query = (const float*)d_in[0];
    const float* key   = (const float*)d_in[1];
    const float* Wq    = (const float*)d_in[2];
    const float* Wk    = (const float*)d_in[3];
    float* out = (float*)d_out;

    (void)in_sizes; (void)n_in; (void)out_size;

    // One-time host resources (streams/events are not device memory).
    static cudaStream_t s2 = nullptr;
    static cudaEvent_t evK[PIPE], evA;
    if (s2 == nullptr) {
        cudaStreamCreateWithFlags(&s2, cudaStreamNonBlocking);
        for (int i = 0; i < PIPE; i++)
            cudaEventCreateWithFlags(&evK[i], cudaEventDisableTiming);
        cudaEventCreateWithFlags(&evA, cudaEventDisableTiming);
    }

    cudaFuncSetAttribute(gemm_tf32_kernel,
                         cudaFuncAttributeMaxDynamicSharedMemorySize,
                         GEMM_SMEM_BYTES);
    cudaFuncSetAttribute(attn_kernel,
                         cudaFuncAttributeMaxDynamicSharedMemorySize,
                         ATTN_SMEM_BYTES);

    void* kp = nullptr; void* qp = nullptr;
    cudaGetSymbolAddress(&kp, g_kproj);
    cudaGetSymbolAddress(&qp, g_qproj);

    // qproj first (attention needs full Q)
    gemm_tf32_kernel<<<dim3((B_ * N_) / 128, C_ / 128), 256, GEMM_SMEM_BYTES>>>(
        query, Wq, (float*)qp, -1);

    // Pipelined kproj chunks (null stream) -> attention chunks (s2)
    const int ROWS_PER_CHUNK = S_ / PIPE;              // 1024
    for (int c = 0; c < PIPE; c++) {
        gemm_tf32_kernel<<<dim3(B_ * ROWS_PER_CHUNK / 128, C_ / 128), 256,
                           GEMM_SMEM_BYTES>>>(key, Wk, (float*)kp,
                                              c * ROWS_PER_CHUNK);
        cudaEventRecord(evK[c], 0);
    }
    for (int c = 0; c < PIPE; c++) {
        cudaStreamWaitEvent(s2, evK[c], 0);
        attn_kernel<<<dim3(NCHUNK / PIPE, H_, B_), 256, ATTN_SMEM_BYTES, s2>>>(
            key, c * (NCHUNK / PIPE));
    }
    cudaEventRecord(evA, s2);
    cudaStreamWaitEvent(0, evA, 0);

    // Reduce chunks + clamp-normalize + duplicate outputs
    finalize_kernel<<<(B_ * N_ * C_) / 256, 256>>>(out);
}

// round 10
// speedup vs baseline: 1.0763x; 1.0763x over previous
#include <cuda_runtime.h>
#include <cstdint>

#define B_ 16
#define N_ 256
#define S_ 4096
#define C_ 512
#define H_ 8
#define HD 64
#define NCHUNK 8
#define SCHUNK (S_ / NCHUNK)   // 512

// Scratch (allocation-free: __device__ globals)
__device__ float g_kproj[(size_t)B_ * S_ * C_];              // 134 MB
__device__ float g_qproj[(size_t)B_ * N_ * C_];              // 8 MB
__device__ float g_opart[(size_t)B_ * H_ * NCHUNK * N_ * HD]; // 32 MB
__device__ float g_divpart[(size_t)B_ * H_ * NCHUNK * N_];

__device__ __forceinline__ uint32_t tf32u(float x) {
    uint32_t u;
    asm("cvt.rna.tf32.f32 %0, %1;" : "=r"(u) : "f"(x));
    return u;
}

__device__ __forceinline__ void mma_tf32(
    float& c0, float& c1, float& c2, float& c3,
    uint32_t a0, uint32_t a1, uint32_t a2, uint32_t a3,
    uint32_t b0, uint32_t b1)
{
    asm volatile(
        "mma.sync.aligned.m16n8k8.row.col.f32.tf32.tf32.f32 "
        "{%0,%1,%2,%3}, {%4,%5,%6,%7}, {%8,%9}, {%0,%1,%2,%3};"
        : "+f"(c0), "+f"(c1), "+f"(c2), "+f"(c3)
        : "r"(a0), "r"(a1), "r"(a2), "r"(a3), "r"(b0), "r"(b1));
}

__device__ __forceinline__ void cp_async16(uint32_t dst, const void* src) {
    asm volatile("cp.async.cg.shared.global [%0], [%1], 16;" :: "r"(dst), "l"(src));
}

// ---------------------------------------------------------------------------
// tf32 tensor-core GEMM with 3-stage cp.async pipeline (R5, known-good).
// ---------------------------------------------------------------------------
#define AS_STRIDE 36
#define WS_STRIDE 136
#define A_FLOATS (128 * AS_STRIDE)
#define STAGE_FLOATS (A_FLOATS + 32 * WS_STRIDE)
#define GEMM_SMEM_BYTES (3 * STAGE_FLOATS * 4)

__global__ __launch_bounds__(256) void gemm_tf32_kernel(
    const float* __restrict__ A, const float* __restrict__ W,
    float* __restrict__ Cout)
{
    extern __shared__ float smbuf[];
    uint32_t smbase;
    {
        uint64_t tmp = __cvta_generic_to_shared(smbuf);
        smbase = (uint32_t)tmp;
    }

    const int tid  = threadIdx.x;
    const int warp = tid >> 5, lane = tid & 31;
    const int wm = warp >> 2, wn = warp & 3;
    const int group = lane >> 2, tid4 = lane & 3;
    const int m0 = blockIdx.x * 128, n0 = blockIdx.y * 128;

    int ar[4], ac4[4], wr[4], wc4[4];
#pragma unroll
    for (int i = 0; i < 4; i++) {
        int f = tid + i * 256;
        ar[i] = f >> 3;  ac4[i] = (f & 7) << 2;
        wr[i] = f >> 5;  wc4[i] = (f & 31) << 2;
    }

    float acc[4][4][4];
#pragma unroll
    for (int mf = 0; mf < 4; mf++)
#pragma unroll
        for (int nf = 0; nf < 4; nf++)
#pragma unroll
            for (int r = 0; r < 4; r++) acc[mf][nf][r] = 0.f;

#define ISSUE_STAGE(kt, s)                                                         \
    do {                                                                           \
        uint32_t sb = smbase + (uint32_t)((s) * STAGE_FLOATS) * 4;                 \
        _Pragma("unroll")                                                          \
        for (int i = 0; i < 4; i++) {                                              \
            cp_async16(sb + (uint32_t)(ar[i] * AS_STRIDE + ac4[i]) * 4,            \
                       A + (size_t)(m0 + ar[i]) * C_ + (kt) * 32 + ac4[i]);        \
            cp_async16(sb + (uint32_t)(A_FLOATS + wr[i] * WS_STRIDE + wc4[i]) * 4, \
                       W + (size_t)((kt) * 32 + wr[i]) * C_ + n0 + wc4[i]);        \
        }                                                                          \
        asm volatile("cp.async.commit_group;");                                    \
    } while (0)

    ISSUE_STAGE(0, 0);
    ISSUE_STAGE(1, 1);

    for (int kt = 0; kt < 16; kt++) {
        const int s = kt % 3;
        if (kt < 14) asm volatile("cp.async.wait_group 1;");
        else         asm volatile("cp.async.wait_group 0;");
        __syncthreads();
        if (kt + 2 < 16) ISSUE_STAGE(kt + 2, (kt + 2) % 3);

        const float* As = smbuf + s * STAGE_FLOATS;
        const float* Ws = As + A_FLOATS;

#pragma unroll
        for (int ks = 0; ks < 4; ks++) {
            const int kb = ks * 8;
            uint32_t a[4][4], b[4][2];
#pragma unroll
            for (int mf = 0; mf < 4; mf++) {
                int r = wm * 64 + mf * 16 + group;
                a[mf][0] = tf32u(As[r * AS_STRIDE + kb + tid4]);
                a[mf][1] = tf32u(As[(r + 8) * AS_STRIDE + kb + tid4]);
                a[mf][2] = tf32u(As[r * AS_STRIDE + kb + tid4 + 4]);
                a[mf][3] = tf32u(As[(r + 8) * AS_STRIDE + kb + tid4 + 4]);
            }
#pragma unroll
            for (int nf = 0; nf < 4; nf++) {
                int c = wn * 32 + nf * 8 + group;
                b[nf][0] = tf32u(Ws[(kb + tid4) * WS_STRIDE + c]);
                b[nf][1] = tf32u(Ws[(kb + tid4 + 4) * WS_STRIDE + c]);
            }
#pragma unroll
            for (int mf = 0; mf < 4; mf++)
#pragma unroll
                for (int nf = 0; nf < 4; nf++)
                    mma_tf32(acc[mf][nf][0], acc[mf][nf][1],
                             acc[mf][nf][2], acc[mf][nf][3],
                             a[mf][0], a[mf][1], a[mf][2], a[mf][3],
                             b[nf][0], b[nf][1]);
        }
    }

#pragma unroll
    for (int mf = 0; mf < 4; mf++) {
#pragma unroll
        for (int nf = 0; nf < 4; nf++) {
            int r = m0 + wm * 64 + mf * 16 + group;
            int c = n0 + wn * 32 + nf * 8 + 2 * tid4;
            *(float2*)(Cout + (size_t)r * C_ + c) =
                make_float2(acc[mf][nf][0], acc[mf][nf][1]);
            *(float2*)(Cout + (size_t)(r + 8) * C_ + c) =
                make_float2(acc[mf][nf][2], acc[mf][nf][3]);
        }
    }
}

// ---------------------------------------------------------------------------
// Attention v4: 512 threads / 16 warps, warp owns 16 q-rows.
// Scores stay in registers: exp in regs, column sums via shfl + small smem,
// attn@V A-fragments built by intra-quad shuffles. K/V tiles double-buffered
// via cp.async. No score smem buffer at all.
// ---------------------------------------------------------------------------
#define ST 68
#define TILE_FLOATS (64 * ST)
// [Ks0][Vs0][Ks1][Vs1][red 16*64][colrcp 64]
#define ATTN_SMEM_FLOATS (4 * TILE_FLOATS + 16 * 64 + 64)
#define ATTN_SMEM_BYTES (ATTN_SMEM_FLOATS * 4)

__global__ __launch_bounds__(512, 1) void attn_kernel(const float* __restrict__ keyv)
{
    extern __shared__ float sm[];
    float* red    = sm + 4 * TILE_FLOATS;   // [16][64]
    float* colrcp = red + 16 * 64;          // [64]

    uint32_t smbase;
    {
        uint64_t tmp = __cvta_generic_to_shared(sm);
        smbase = (uint32_t)tmp;
    }

    const int tid = threadIdx.x;
    const int warp = tid >> 5, lane = tid & 31;
    const int g = lane >> 2, t4 = lane & 3;
    const int chk = blockIdx.x, h = blockIdx.y, b = blockIdx.z;
    const int rb = warp * 16;               // warp's 16 query rows

    // Q fragments (scale folded): rows rb+g, rb+8+g; cols kb*8+t4, +4
    uint32_t qa[8][4];
    {
        const float* qp = g_qproj + (size_t)b * N_ * C_ + h * HD;
#pragma unroll
        for (int kb = 0; kb < 8; kb++) {
            qa[kb][0] = tf32u(qp[(size_t)(rb + g) * C_ + kb * 8 + t4] * 0.125f);
            qa[kb][1] = tf32u(qp[(size_t)(rb + 8 + g) * C_ + kb * 8 + t4] * 0.125f);
            qa[kb][2] = tf32u(qp[(size_t)(rb + g) * C_ + kb * 8 + t4 + 4] * 0.125f);
            qa[kb][3] = tf32u(qp[(size_t)(rb + 8 + g) * C_ + kb * 8 + t4 + 4] * 0.125f);
        }
    }

    float oa[8][4];
#pragma unroll
    for (int nf = 0; nf < 8; nf++)
#pragma unroll
        for (int r = 0; r < 4; r++) oa[nf][r] = 0.f;
    float dv0 = 0.f, dv1 = 0.f;

    // Tile load: 512 thr x 2 float4 per tile buffer pair (2048 float4 total)
    const size_t kvbase = (size_t)b * S_ * C_ + h * HD;

#define ISSUE_TILE(t)                                                          \
    do {                                                                       \
        int bufsel = (t) & 1;                                                  \
        uint32_t kb_ = smbase + (uint32_t)(2 * bufsel * TILE_FLOATS) * 4;      \
        uint32_t vb_ = kb_ + (uint32_t)TILE_FLOATS * 4;                        \
        int s0_ = chk * SCHUNK + (t) * 64;                                     \
        _Pragma("unroll")                                                      \
        for (int i = 0; i < 2; i++) {                                          \
            int f = tid + i * 512;                                             \
            int row = f >> 4, c4 = (f & 15) << 2;                              \
            size_t gb = kvbase + (size_t)(s0_ + row) * C_ + c4;                \
            cp_async16(kb_ + (uint32_t)(row * ST + c4) * 4, g_kproj + gb);     \
            cp_async16(vb_ + (uint32_t)(row * ST + c4) * 4, keyv + gb);        \
        }                                                                      \
        asm volatile("cp.async.commit_group;");                                \
    } while (0)

    ISSUE_TILE(0);

    for (int tile = 0; tile < SCHUNK / 64; tile++) {
        if (tile + 1 < SCHUNK / 64) {
            ISSUE_TILE(tile + 1);
            asm volatile("cp.async.wait_group 1;");
        } else {
            asm volatile("cp.async.wait_group 0;");
        }
        __syncthreads();

        const float* Ks = sm + 2 * (tile & 1) * TILE_FLOATS;
        const float* Vs = Ks + TILE_FLOATS;

        // scores = Q_frag @ K_tile^T  (rows rb+g/rb+8+g, cols nf*8+2t4/+1)
        float e[8][4];
#pragma unroll
        for (int nf = 0; nf < 8; nf++)
#pragma unroll
            for (int r = 0; r < 4; r++) e[nf][r] = 0.f;
#pragma unroll
        for (int kb = 0; kb < 8; kb++) {
            uint32_t bfr[8][2];
#pragma unroll
            for (int nf = 0; nf < 8; nf++) {
                bfr[nf][0] = tf32u(Ks[(nf * 8 + g) * ST + kb * 8 + t4]);
                bfr[nf][1] = tf32u(Ks[(nf * 8 + g) * ST + kb * 8 + t4 + 4]);
            }
#pragma unroll
            for (int nf = 0; nf < 8; nf++)
                mma_tf32(e[nf][0], e[nf][1], e[nf][2], e[nf][3],
                         qa[kb][0], qa[kb][1], qa[kb][2], qa[kb][3],
                         bfr[nf][0], bfr[nf][1]);
        }

        // exp in registers + per-warp column partial sums
#pragma unroll
        for (int nf = 0; nf < 8; nf++) {
            e[nf][0] = __expf(e[nf][0]);
            e[nf][1] = __expf(e[nf][1]);
            e[nf][2] = __expf(e[nf][2]);
            e[nf][3] = __expf(e[nf][3]);
            float se = e[nf][0] + e[nf][2];   // col 2t4   (rows g, g+8)
            float so = e[nf][1] + e[nf][3];   // col 2t4+1
            se += __shfl_xor_sync(0xFFFFFFFF, se, 4);
            so += __shfl_xor_sync(0xFFFFFFFF, so, 4);
            se += __shfl_xor_sync(0xFFFFFFFF, se, 8);
            so += __shfl_xor_sync(0xFFFFFFFF, so, 8);
            se += __shfl_xor_sync(0xFFFFFFFF, se, 16);
            so += __shfl_xor_sync(0xFFFFFFFF, so, 16);
            if (g == 0) {
                red[warp * 64 + nf * 8 + 2 * t4] = se;
                red[warp * 64 + nf * 8 + 2 * t4 + 1] = so;
            }
        }
        __syncthreads();

        if (tid < 64) {
            float s = 0.f;
#pragma unroll
            for (int w = 0; w < 16; w++) s += red[w * 64 + tid];
            colrcp[tid] = 1.0f / s;
        }
        __syncthreads();

        // attn @ V : A-frags built from e[] via intra-quad shuffles
        const int half = t4 >> 1;
        const int lane_lo = (lane & ~3) | half;     // source for col t4
        const int lane_hi = lane_lo + 2;            // source for col t4+4
        const bool odd = (t4 & 1);
#pragma unroll
        for (int kb = 0; kb < 8; kb++) {
            float cr0 = colrcp[kb * 8 + t4], cr1 = colrcp[kb * 8 + t4 + 4];
            float v;
            // f0: row g, col t4
            float a = __shfl_sync(0xFFFFFFFF, e[kb][0], lane_lo);
            v       = __shfl_sync(0xFFFFFFFF, e[kb][1], lane_lo);
            float f0 = (odd ? v : a) * cr0;
            // f1: row g+8, col t4
            a = __shfl_sync(0xFFFFFFFF, e[kb][2], lane_lo);
            v = __shfl_sync(0xFFFFFFFF, e[kb][3], lane_lo);
            float f1 = (odd ? v : a) * cr0;
            // f2: row g, col t4+4
            a = __shfl_sync(0xFFFFFFFF, e[kb][0], lane_hi);
            v = __shfl_sync(0xFFFFFFFF, e[kb][1], lane_hi);
            float f2 = (odd ? v : a) * cr1;
            // f3: row g+8, col t4+4
            a = __shfl_sync(0xFFFFFFFF, e[kb][2], lane_hi);
            v = __shfl_sync(0xFFFFFFFF, e[kb][3], lane_hi);
            float f3 = (odd ? v : a) * cr1;

            dv0 += f0 + f2;
            dv1 += f1 + f3;

            uint32_t a0 = tf32u(f0), a1 = tf32u(f1), a2 = tf32u(f2), a3 = tf32u(f3);
            uint32_t bfr[8][2];
#pragma unroll
            for (int nf = 0; nf < 8; nf++) {
                bfr[nf][0] = tf32u(Vs[(kb * 8 + t4) * ST + nf * 8 + g]);
                bfr[nf][1] = tf32u(Vs[(kb * 8 + t4 + 4) * ST + nf * 8 + g]);
            }
#pragma unroll
            for (int nf = 0; nf < 8; nf++)
                mma_tf32(oa[nf][0], oa[nf][1], oa[nf][2], oa[nf][3],
                         a0, a1, a2, a3, bfr[nf][0], bfr[nf][1]);
        }
        __syncthreads();   // protect red/colrcp + K/V buffer reuse
    }

    // Divisor: reduce over the 4 t4-lanes of each quad
    {
        float v = dv0;
        v += __shfl_xor_sync(0xFFFFFFFF, v, 1);
        v += __shfl_xor_sync(0xFFFFFFFF, v, 2);
        float w2 = dv1;
        w2 += __shfl_xor_sync(0xFFFFFFFF, w2, 1);
        w2 += __shfl_xor_sync(0xFFFFFFFF, w2, 2);
        if (t4 == 0) {
            size_t base = (size_t)((b * H_ + h) * NCHUNK + chk) * N_;
            g_divpart[base + rb + g] = v;
            g_divpart[base + rb + 8 + g] = w2;
        }
    }

    // O partials
    const size_t pbase = (size_t)((b * H_ + h) * NCHUNK + chk) * N_;
#pragma unroll
    for (int nf = 0; nf < 8; nf++) {
        int c = nf * 8 + 2 * t4;
        *(float2*)(g_opart + (pbase + rb + g) * HD + c) =
            make_float2(oa[nf][0], oa[nf][1]);
        *(float2*)(g_opart + (pbase + rb + 8 + g) * HD + c) =
            make_float2(oa[nf][2], oa[nf][3]);
    }
}

// ---------------------------------------------------------------------------
__global__ __launch_bounds__(256) void finalize_kernel(float* __restrict__ out)
{
    int idx = blockIdx.x * 256 + threadIdx.x;
    int c512 = idx & 511;
    int n = (idx >> 9) & 255;
    int b = idx >> 17;
    int h = c512 >> 6, c = c512 & 63;
    float acc = 0.f, dvs = 0.f;
#pragma unroll
    for (int chk = 0; chk < NCHUNK; chk++) {
        size_t pidx = (size_t)((b * H_ + h) * NCHUNK + chk) * N_ + n;
        acc += g_opart[pidx * HD + c];
        dvs += g_divpart[pidx];
    }
    float r = acc / fmaxf(dvs, 1.0f);
    out[idx] = r;
    out[idx + (size_t)B_ * N_ * C_] = r;
}

// ---------------------------------------------------------------------------
extern "C" void kernel_launch(void* const* d_in, const int* in_sizes, int n_in,
                              void* d_out, int out_size)
{
    const float* query = (const float*)d_in[0];
    const float* key   = (const float*)d_in[1];
    const float* Wq    = (const float*)d_in[2];
    const float* Wk    = (const float*)d_in[3];
    float* out = (float*)d_out;

    (void)in_sizes; (void)n_in; (void)out_size;

    cudaFuncSetAttribute(gemm_tf32_kernel,
                         cudaFuncAttributeMaxDynamicSharedMemorySize,
                         GEMM_SMEM_BYTES);
    cudaFuncSetAttribute(attn_kernel,
                         cudaFuncAttributeMaxDynamicSharedMemorySize,
                         ATTN_SMEM_BYTES);

    void* kp = nullptr; void* qp = nullptr;
    cudaGetSymbolAddress(&kp, g_kproj);
    cudaGetSymbolAddress(&qp, g_qproj);

    // Projections on tensor cores (tf32, cp.async pipelined) — sequential (R5)
    gemm_tf32_kernel<<<dim3((B_ * S_) / 128, C_ / 128), 256, GEMM_SMEM_BYTES>>>(
        key, Wk, (float*)kp);
    gemm_tf32_kernel<<<dim3((B_ * N_) / 128, C_ / 128), 256, GEMM_SMEM_BYTES>>>(
        query, Wq, (float*)qp);

    // Attention: register-resident scores, 16 warps, double-buffered tiles
    attn_kernel<<<dim3(NCHUNK, H_, B_), 512, ATTN_SMEM_BYTES>>>(key);

    // Reduce chunks + clamp-normalize + duplicate outputs
    finalize_kernel<<<(B_ * N_ * C_) / 256, 256>>>(out);
}

// round 13
// speedup vs baseline: 1.1173x; 1.0381x over previous
#include <cuda_runtime.h>
#include <cstdint>

#define B_ 16
#define N_ 256
#define S_ 4096
#define C_ 512
#define H_ 8
#define HD 64
#define NCHUNK 8
#define SCHUNK (S_ / NCHUNK)   // 512

// Scratch (allocation-free: __device__ globals)
__device__ float g_kproj[(size_t)B_ * S_ * C_];              // 134 MB
__device__ float g_qproj[(size_t)B_ * N_ * C_];              // 8 MB
__device__ float g_opart[(size_t)B_ * H_ * NCHUNK * N_ * HD]; // 32 MB
__device__ float g_divpart[(size_t)B_ * H_ * NCHUNK * N_];

__device__ __forceinline__ uint32_t tf32u(float x) {
    uint32_t u;
    asm("cvt.rna.tf32.f32 %0, %1;" : "=r"(u) : "f"(x));
    return u;
}

__device__ __forceinline__ void mma_tf32(
    float& c0, float& c1, float& c2, float& c3,
    uint32_t a0, uint32_t a1, uint32_t a2, uint32_t a3,
    uint32_t b0, uint32_t b1)
{
    asm volatile(
        "mma.sync.aligned.m16n8k8.row.col.f32.tf32.tf32.f32 "
        "{%0,%1,%2,%3}, {%4,%5,%6,%7}, {%8,%9}, {%0,%1,%2,%3};"
        : "+f"(c0), "+f"(c1), "+f"(c2), "+f"(c3)
        : "r"(a0), "r"(a1), "r"(a2), "r"(a3), "r"(b0), "r"(b1));
}

__device__ __forceinline__ void cp_async16(uint32_t dst, const void* src) {
    asm volatile("cp.async.cg.shared.global [%0], [%1], 16;" :: "r"(dst), "l"(src));
}

// ---------------------------------------------------------------------------
// tf32 tensor-core GEMM, 2-stage cp.async pipeline, 2 CTAs/SM.
// C[M,512] = A[M,512] @ W[512,512]; block 128x128, 8 warps, warp 64x32, K-tile 32.
// ---------------------------------------------------------------------------
#define AS_STRIDE 36
#define WS_STRIDE 136
#define A_FLOATS (128 * AS_STRIDE)
#define STAGE_FLOATS (A_FLOATS + 32 * WS_STRIDE)   // 8960 floats = 35840 B
#define GEMM_SMEM_BYTES (2 * STAGE_FLOATS * 4)     // 71680 B -> 2 CTAs/SM

__global__ __launch_bounds__(256, 2) void gemm_tf32_kernel(
    const float* __restrict__ A, const float* __restrict__ W,
    float* __restrict__ Cout)
{
    extern __shared__ float smbuf[];
    uint32_t smbase;
    {
        uint64_t tmp = __cvta_generic_to_shared(smbuf);
        smbase = (uint32_t)tmp;
    }

    const int tid  = threadIdx.x;
    const int warp = tid >> 5, lane = tid & 31;
    const int wm = warp >> 2, wn = warp & 3;
    const int group = lane >> 2, tid4 = lane & 3;
    const int m0 = blockIdx.x * 128, n0 = blockIdx.y * 128;

    int ar[4], ac4[4], wr[4], wc4[4];
#pragma unroll
    for (int i = 0; i < 4; i++) {
        int f = tid + i * 256;
        ar[i] = f >> 3;  ac4[i] = (f & 7) << 2;
        wr[i] = f >> 5;  wc4[i] = (f & 31) << 2;
    }

    float acc[4][4][4];
#pragma unroll
    for (int mf = 0; mf < 4; mf++)
#pragma unroll
        for (int nf = 0; nf < 4; nf++)
#pragma unroll
            for (int r = 0; r < 4; r++) acc[mf][nf][r] = 0.f;

#define ISSUE_STAGE(kt, s)                                                         \
    do {                                                                           \
        uint32_t sb = smbase + (uint32_t)((s) * STAGE_FLOATS) * 4;                 \
        _Pragma("unroll")                                                          \
        for (int i = 0; i < 4; i++) {                                              \
            cp_async16(sb + (uint32_t)(ar[i] * AS_STRIDE + ac4[i]) * 4,            \
                       A + (size_t)(m0 + ar[i]) * C_ + (kt) * 32 + ac4[i]);        \
            cp_async16(sb + (uint32_t)(A_FLOATS + wr[i] * WS_STRIDE + wc4[i]) * 4, \
                       W + (size_t)((kt) * 32 + wr[i]) * C_ + n0 + wc4[i]);        \
        }                                                                          \
        asm volatile("cp.async.commit_group;");                                    \
    } while (0)

    ISSUE_STAGE(0, 0);

    for (int kt = 0; kt < 16; kt++) {
        if (kt + 1 < 16) {
            ISSUE_STAGE(kt + 1, (kt + 1) & 1);
            asm volatile("cp.async.wait_group 1;");
        } else {
            asm volatile("cp.async.wait_group 0;");
        }
        __syncthreads();   // stage kt visible to all warps

        const float* As = smbuf + (kt & 1) * STAGE_FLOATS;
        const float* Ws = As + A_FLOATS;

#pragma unroll
        for (int ks = 0; ks < 4; ks++) {
            const int kb = ks * 8;
            uint32_t a[4][4], b[4][2];
#pragma unroll
            for (int mf = 0; mf < 4; mf++) {
                int r = wm * 64 + mf * 16 + group;
                a[mf][0] = tf32u(As[r * AS_STRIDE + kb + tid4]);
                a[mf][1] = tf32u(As[(r + 8) * AS_STRIDE + kb + tid4]);
                a[mf][2] = tf32u(As[r * AS_STRIDE + kb + tid4 + 4]);
                a[mf][3] = tf32u(As[(r + 8) * AS_STRIDE + kb + tid4 + 4]);
            }
#pragma unroll
            for (int nf = 0; nf < 4; nf++) {
                int c = wn * 32 + nf * 8 + group;
                b[nf][0] = tf32u(Ws[(kb + tid4) * WS_STRIDE + c]);
                b[nf][1] = tf32u(Ws[(kb + tid4 + 4) * WS_STRIDE + c]);
            }
#pragma unroll
            for (int mf = 0; mf < 4; mf++)
#pragma unroll
                for (int nf = 0; nf < 4; nf++)
                    mma_tf32(acc[mf][nf][0], acc[mf][nf][1],
                             acc[mf][nf][2], acc[mf][nf][3],
                             a[mf][0], a[mf][1], a[mf][2], a[mf][3],
                             b[nf][0], b[nf][1]);
        }
        __syncthreads();   // all reads done before next ISSUE overwrites buffer
    }

#pragma unroll
    for (int mf = 0; mf < 4; mf++) {
#pragma unroll
        for (int nf = 0; nf < 4; nf++) {
            int r = m0 + wm * 64 + mf * 16 + group;
            int c = n0 + wn * 32 + nf * 8 + 2 * tid4;
            *(float2*)(Cout + (size_t)r * C_ + c) =
                make_float2(acc[mf][nf][0], acc[mf][nf][1]);
            *(float2*)(Cout + (size_t)(r + 8) * C_ + c) =
                make_float2(acc[mf][nf][2], acc[mf][nf][3]);
        }
    }
}

// ---------------------------------------------------------------------------
// Attention (exact R5 body — the 614 us configuration).
// ---------------------------------------------------------------------------
#define ST 68
#define ATTN_SMEM_FLOATS (256 * ST + 64 * ST + 64 * ST + 256 + 64)
#define ATTN_SMEM_BYTES (ATTN_SMEM_FLOATS * 4)

__global__ __launch_bounds__(256) void attn_kernel(const float* __restrict__ keyv)
{
    extern __shared__ float sm[];
    float* sc     = sm;                 // [256][ST]
    float* Ks     = sm + 256 * ST;      // [64][ST]
    float* Vs     = Ks + 64 * ST;       // [64][ST]
    float* red    = Vs + 64 * ST;       // [4][64]
    float* colrcp = red + 256;          // [64]

    const int tid = threadIdx.x;
    const int warp = tid >> 5, lane = tid & 31;
    const int g = lane >> 2, t4 = lane & 3;
    const int chk = blockIdx.x, h = blockIdx.y, b = blockIdx.z;
    const int rb = warp * 32;
    const int col = tid & 63, part = tid >> 6;

    uint32_t qa[2][8][4];
    {
        const float* qp = g_qproj + (size_t)b * N_ * C_ + h * HD;
#pragma unroll
        for (int mf = 0; mf < 2; mf++) {
            int r0 = rb + mf * 16 + g;
#pragma unroll
            for (int kb = 0; kb < 8; kb++) {
                qa[mf][kb][0] = tf32u(qp[(size_t)r0 * C_ + kb * 8 + t4] * 0.125f);
                qa[mf][kb][1] = tf32u(qp[(size_t)(r0 + 8) * C_ + kb * 8 + t4] * 0.125f);
                qa[mf][kb][2] = tf32u(qp[(size_t)r0 * C_ + kb * 8 + t4 + 4] * 0.125f);
                qa[mf][kb][3] = tf32u(qp[(size_t)(r0 + 8) * C_ + kb * 8 + t4 + 4] * 0.125f);
            }
        }
    }

    float oa[2][8][4];
#pragma unroll
    for (int mf = 0; mf < 2; mf++)
#pragma unroll
        for (int nf = 0; nf < 8; nf++)
#pragma unroll
            for (int r = 0; r < 4; r++) oa[mf][nf][r] = 0.f;
    float dv[2][2] = {{0.f, 0.f}, {0.f, 0.f}};

    for (int tile = 0; tile < SCHUNK / 64; tile++) {
        const int s0 = chk * SCHUNK + tile * 64;
#pragma unroll
        for (int i = 0; i < 4; i++) {
            int f = tid + i * 256;
            int row = f >> 4, c4 = (f & 15) << 2;
            size_t gb = (size_t)(b * S_ + s0 + row) * C_ + h * HD + c4;
            *(float4*)&Ks[row * ST + c4] = *(const float4*)(g_kproj + gb);
            *(float4*)&Vs[row * ST + c4] = *(const float4*)(keyv + gb);
        }
        __syncthreads();

        float sacc[2][8][4];
#pragma unroll
        for (int mf = 0; mf < 2; mf++)
#pragma unroll
            for (int nf = 0; nf < 8; nf++)
#pragma unroll
                for (int r = 0; r < 4; r++) sacc[mf][nf][r] = 0.f;
#pragma unroll
        for (int kb = 0; kb < 8; kb++) {
            uint32_t bfr[8][2];
#pragma unroll
            for (int nf = 0; nf < 8; nf++) {
                bfr[nf][0] = tf32u(Ks[(nf * 8 + g) * ST + kb * 8 + t4]);
                bfr[nf][1] = tf32u(Ks[(nf * 8 + g) * ST + kb * 8 + t4 + 4]);
            }
#pragma unroll
            for (int mf = 0; mf < 2; mf++)
#pragma unroll
                for (int nf = 0; nf < 8; nf++)
                    mma_tf32(sacc[mf][nf][0], sacc[mf][nf][1],
                             sacc[mf][nf][2], sacc[mf][nf][3],
                             qa[mf][kb][0], qa[mf][kb][1], qa[mf][kb][2], qa[mf][kb][3],
                             bfr[nf][0], bfr[nf][1]);
        }
#pragma unroll
        for (int mf = 0; mf < 2; mf++)
#pragma unroll
            for (int nf = 0; nf < 8; nf++) {
                int r = rb + mf * 16 + g;
                int c = nf * 8 + 2 * t4;
                *(float2*)&sc[r * ST + c] = make_float2(sacc[mf][nf][0], sacc[mf][nf][1]);
                *(float2*)&sc[(r + 8) * ST + c] = make_float2(sacc[mf][nf][2], sacc[mf][nf][3]);
            }
        __syncthreads();

        float psum = 0.f;
#pragma unroll 4
        for (int r = 0; r < 64; r++) {
            int i = (part * 64 + r) * ST + col;
            float e = __expf(sc[i]);
            sc[i] = e;
            psum += e;
        }
        red[part * 64 + col] = psum;
        __syncthreads();
        if (part == 0)
            colrcp[col] = 1.0f / (red[col] + red[64 + col] + red[128 + col] + red[192 + col]);
        __syncthreads();

#pragma unroll
        for (int kb = 0; kb < 8; kb++) {
            float cr0 = colrcp[kb * 8 + t4], cr1 = colrcp[kb * 8 + t4 + 4];
            uint32_t afr[2][4];
#pragma unroll
            for (int mf = 0; mf < 2; mf++) {
                int r = rb + mf * 16 + g;
                float f0 = sc[r * ST + kb * 8 + t4] * cr0;
                float f1 = sc[(r + 8) * ST + kb * 8 + t4] * cr0;
                float f2 = sc[r * ST + kb * 8 + t4 + 4] * cr1;
                float f3 = sc[(r + 8) * ST + kb * 8 + t4 + 4] * cr1;
                dv[mf][0] += f0 + f2;
                dv[mf][1] += f1 + f3;
                afr[mf][0] = tf32u(f0); afr[mf][1] = tf32u(f1);
                afr[mf][2] = tf32u(f2); afr[mf][3] = tf32u(f3);
            }
            uint32_t bfr[8][2];
#pragma unroll
            for (int nf = 0; nf < 8; nf++) {
                bfr[nf][0] = tf32u(Vs[(kb * 8 + t4) * ST + nf * 8 + g]);
                bfr[nf][1] = tf32u(Vs[(kb * 8 + t4 + 4) * ST + nf * 8 + g]);
            }
#pragma unroll
            for (int mf = 0; mf < 2; mf++)
#pragma unroll
                for (int nf = 0; nf < 8; nf++)
                    mma_tf32(oa[mf][nf][0], oa[mf][nf][1],
                             oa[mf][nf][2], oa[mf][nf][3],
                             afr[mf][0], afr[mf][1], afr[mf][2], afr[mf][3],
                             bfr[nf][0], bfr[nf][1]);
        }
        __syncthreads();
    }

#pragma unroll
    for (int mf = 0; mf < 2; mf++)
#pragma unroll
        for (int hh = 0; hh < 2; hh++) {
            float v = dv[mf][hh];
            v += __shfl_xor_sync(0xFFFFFFFF, v, 1);
            v += __shfl_xor_sync(0xFFFFFFFF, v, 2);
            if (t4 == 0) {
                int row = rb + mf * 16 + hh * 8 + g;
                g_divpart[(size_t)((b * H_ + h) * NCHUNK + chk) * N_ + row] = v;
            }
        }

    const size_t pbase = (size_t)((b * H_ + h) * NCHUNK + chk) * N_;
#pragma unroll
    for (int mf = 0; mf < 2; mf++)
#pragma unroll
        for (int nf = 0; nf < 8; nf++) {
            int r = rb + mf * 16 + g;
            int c = nf * 8 + 2 * t4;
            *(float2*)(g_opart + (pbase + r) * HD + c) =
                make_float2(oa[mf][nf][0], oa[mf][nf][1]);
            *(float2*)(g_opart + (pbase + r + 8) * HD + c) =
                make_float2(oa[mf][nf][2], oa[mf][nf][3]);
        }
}

// ---------------------------------------------------------------------------
__global__ __launch_bounds__(256) void finalize_kernel(float* __restrict__ out)
{
    int idx = blockIdx.x * 256 + threadIdx.x;
    int c512 = idx & 511;
    int n = (idx >> 9) & 255;
    int b = idx >> 17;
    int h = c512 >> 6, c = c512 & 63;
    float acc = 0.f, dvs = 0.f;
#pragma unroll
    for (int chk = 0; chk < NCHUNK; chk++) {
        size_t pidx = (size_t)((b * H_ + h) * NCHUNK + chk) * N_ + n;
        acc += g_opart[pidx * HD + c];
        dvs += g_divpart[pidx];
    }
    float r = acc / fmaxf(dvs, 1.0f);
    out[idx] = r;
    out[idx + (size_t)B_ * N_ * C_] = r;
}

// ---------------------------------------------------------------------------
extern "C" void kernel_launch(void* const* d_in, const int* in_sizes, int n_in,
                              void* d_out, int out_size)
{
    const float* query = (const float*)d_in[0];
    const float* key   = (const float*)d_in[1];
    const float* Wq    = (const float*)d_in[2];
    const float* Wk    = (const float*)d_in[3];
    float* out = (float*)d_out;

    (void)in_sizes; (void)n_in; (void)out_size;

    cudaFuncSetAttribute(gemm_tf32_kernel,
                         cudaFuncAttributeMaxDynamicSharedMemorySize,
                         GEMM_SMEM_BYTES);
    cudaFuncSetAttribute(attn_kernel,
                         cudaFuncAttributeMaxDynamicSharedMemorySize,
                         ATTN_SMEM_BYTES);

    void* kp = nullptr; void* qp = nullptr;
    cudaGetSymbolAddress(&kp, g_kproj);
    cudaGetSymbolAddress(&qp, g_qproj);

    // Projections on tensor cores (tf32, 2-stage cp.async, 2 CTAs/SM)
    gemm_tf32_kernel<<<dim3((B_ * S_) / 128, C_ / 128), 256, GEMM_SMEM_BYTES>>>(
        key, Wk, (float*)kp);
    gemm_tf32_kernel<<<dim3((B_ * N_) / 128, C_ / 128), 256, GEMM_SMEM_BYTES>>>(
        query, Wq, (float*)qp);

    // Attention (tensor-core, streaming over S chunks) — R5 body
    attn_kernel<<<dim3(NCHUNK, H_, B_), 256, ATTN_SMEM_BYTES>>>(key);

    // Reduce chunks + clamp-normalize + duplicate outputs
    finalize_kernel<<<(B_ * N_ * C_) / 256, 256>>>(out);
}